// round 1
// baseline (speedup 1.0000x reference)
#include <cuda_runtime.h>
#include <stdint.h>

#define THREADS 512
#define CAP 1024   // candidate list capacity per side (fallback to full scan if exceeded)

// Order-preserving float -> uint32 mapping (ascending)
__device__ __forceinline__ unsigned f2key(float f) {
    unsigned u = __float_as_uint(f);
    return u ^ ((unsigned)((int)u >> 31) | 0x80000000u);
}

__global__ __launch_bounds__(THREADS, 4)
void topk_mask_kernel(const float* __restrict__ x, const float* __restrict__ w,
                      const int* __restrict__ kp, float* __restrict__ out,
                      int Fdim)
{
    __shared__ __align__(16) float row[8192];
    __shared__ unsigned histA[256];
    __shared__ unsigned histB[256];
    __shared__ int listH[CAP];
    __shared__ int listL[CAP];
    __shared__ int cntH, cntL;
    __shared__ unsigned s_prefix_hi, s_prefix_lo;
    __shared__ int s_r_hi, s_r_lo;
    __shared__ unsigned s_ceq_hi, s_ceq_lo;

    const int tid  = threadIdx.x;
    const int lane = tid & 31;
    const int warp = tid >> 5;
    const int b    = blockIdx.x;
    const int K    = kp ? kp[0] : 64;

    const float4* xr = (const float4*)(x + (size_t)b * Fdim);
    const float4* wr = (const float4*)w;
    float4* orow     = (float4*)(out + (size_t)b * Fdim);
    const int nvec   = Fdim >> 2;

    if (tid == 0) { cntH = 0; cntL = 0; }
    for (int i = tid; i < 256; i += THREADS) histA[i] = 0;
    __syncthreads();

    // ---- Phase 0: load + multiply + byte-3 histogram (warp-aggregated) ----
    for (int v0 = 0; v0 < nvec; v0 += THREADS) {
        int v = v0 + tid;
        bool valid = v < nvec;
        float4 r = make_float4(0.f, 0.f, 0.f, 0.f);
        if (valid) {
            float4 xv = xr[v];
            float4 wv = wr[v];
            r.x = xv.x * wv.x; r.y = xv.y * wv.y;
            r.z = xv.z * wv.z; r.w = xv.w * wv.w;
            ((float4*)row)[v] = r;
        }
        float comp[4] = { r.x, r.y, r.z, r.w };
        #pragma unroll
        for (int c = 0; c < 4; c++) {
            unsigned bin = valid ? (f2key(comp[c]) >> 24) : 0xFFFFFFFFu;
            unsigned m = __match_any_sync(0xFFFFFFFFu, bin);
            if (valid && lane == (__ffs(m) - 1))
                atomicAdd(&histA[bin], (unsigned)__popc(m));
        }
    }
    __syncthreads();

    // ---- Phase 1: resolve byte-3 bins. warp0 = top side (suffix), warp1 = bottom (prefix)
    if (warp == 0) {
        unsigned cnt[8], s = 0;
        #pragma unroll
        for (int j = 0; j < 8; j++) { cnt[j] = histA[lane * 8 + j]; s += cnt[j]; }
        unsigned acc = s;
        #pragma unroll
        for (int off = 1; off < 32; off <<= 1) {
            unsigned vv = __shfl_down_sync(0xFFFFFFFFu, acc, off);
            if (lane + off < 32) acc += vv;
        }
        unsigned run = acc - s;   // count in lanes strictly above
        int r = K;
        #pragma unroll
        for (int j = 7; j >= 0; j--) {
            unsigned c = cnt[j];
            if ((int)run < r && (int)(run + c) >= r) {
                s_prefix_hi = (unsigned)(lane * 8 + j);
                s_r_hi = r - (int)run;
                s_ceq_hi = c;
            }
            run += c;
        }
    } else if (warp == 1) {
        unsigned cnt[8], s = 0;
        #pragma unroll
        for (int j = 0; j < 8; j++) { cnt[j] = histA[lane * 8 + j]; s += cnt[j]; }
        unsigned acc = s;
        #pragma unroll
        for (int off = 1; off < 32; off <<= 1) {
            unsigned vv = __shfl_up_sync(0xFFFFFFFFu, acc, off);
            if (lane >= off) acc += vv;
        }
        unsigned run = acc - s;   // count in lanes strictly below
        int r = K;
        #pragma unroll
        for (int j = 0; j < 8; j++) {
            unsigned c = cnt[j];
            if ((int)run < r && (int)(run + c) >= r) {
                s_prefix_lo = (unsigned)(lane * 8 + j);
                s_r_lo = r - (int)run;
                s_ceq_lo = c;
            }
            run += c;
        }
    }
    __syncthreads();

    // ---- Phase 2: compact candidate indices for both boundary bins ----
    {
        unsigned b3h = s_prefix_hi, b3l = s_prefix_lo;
        for (int i = tid; i < Fdim; i += THREADS) {
            unsigned b3 = f2key(row[i]) >> 24;
            if (b3 == b3h) { int p = atomicAdd(&cntH, 1); if (p < CAP) listH[p] = i; }
            if (b3 == b3l) { int p = atomicAdd(&cntL, 1); if (p < CAP) listL[p] = i; }
        }
    }
    __syncthreads();
    const bool okH = (cntH <= CAP), okL = (cntL <= CAP);
    const int nH = okH ? cntH : Fdim;
    const int nL = okL ? cntL : Fdim;

    // ---- Phases 3-5: radix passes on bytes 2,1,0 over candidates ----
    for (int p = 2; p >= 0; p--) {
        for (int i = tid; i < 256; i += THREADS) { histA[i] = 0; histB[i] = 0; }
        __syncthreads();
        unsigned ph = s_prefix_hi, pl = s_prefix_lo;
        int shift = (p + 1) * 8;

        for (int j = tid; j < nH; j += THREADS) {
            int i = okH ? listH[j] : j;
            unsigned key = f2key(row[i]);
            if ((key >> shift) == ph) atomicAdd(&histA[(key >> (p * 8)) & 255], 1u);
        }
        for (int j = tid; j < nL; j += THREADS) {
            int i = okL ? listL[j] : j;
            unsigned key = f2key(row[i]);
            if ((key >> shift) == pl) atomicAdd(&histB[(key >> (p * 8)) & 255], 1u);
        }
        __syncthreads();

        if (warp == 0) {
            unsigned cnt[8], s = 0;
            #pragma unroll
            for (int j = 0; j < 8; j++) { cnt[j] = histA[lane * 8 + j]; s += cnt[j]; }
            unsigned acc = s;
            #pragma unroll
            for (int off = 1; off < 32; off <<= 1) {
                unsigned vv = __shfl_down_sync(0xFFFFFFFFu, acc, off);
                if (lane + off < 32) acc += vv;
            }
            unsigned run = acc - s;
            int r = s_r_hi;
            #pragma unroll
            for (int j = 7; j >= 0; j--) {
                unsigned c = cnt[j];
                if ((int)run < r && (int)(run + c) >= r) {
                    s_prefix_hi = (ph << 8) | (unsigned)(lane * 8 + j);
                    s_r_hi = r - (int)run;
                    s_ceq_hi = c;
                }
                run += c;
            }
        } else if (warp == 1) {
            unsigned cnt[8], s = 0;
            #pragma unroll
            for (int j = 0; j < 8; j++) { cnt[j] = histB[lane * 8 + j]; s += cnt[j]; }
            unsigned acc = s;
            #pragma unroll
            for (int off = 1; off < 32; off <<= 1) {
                unsigned vv = __shfl_up_sync(0xFFFFFFFFu, acc, off);
                if (lane >= off) acc += vv;
            }
            unsigned run = acc - s;
            int r = s_r_lo;
            #pragma unroll
            for (int j = 0; j < 8; j++) {
                unsigned c = cnt[j];
                if ((int)run < r && (int)(run + c) >= r) {
                    s_prefix_lo = (pl << 8) | (unsigned)(lane * 8 + j);
                    s_r_lo = r - (int)run;
                    s_ceq_lo = c;
                }
                run += c;
            }
        }
        __syncthreads();
    }

    // ---- Phase 6: masked write-out ----
    const unsigned Th = s_prefix_hi, Tl = s_prefix_lo;
    const int rh = s_r_hi, rl = s_r_lo;
    const bool ordH = (s_ceq_hi != (unsigned)rh);  // rare: ties straddle rank boundary
    const bool ordL = (s_ceq_lo != (unsigned)rl);

    for (int v = tid; v < nvec; v += THREADS) {
        float4 r = ((float4*)row)[v];
        float vals[4] = { r.x, r.y, r.z, r.w };
        #pragma unroll
        for (int c = 0; c < 4; c++) {
            unsigned key = f2key(vals[c]);
            bool z = (key > Th) || (key < Tl);
            if (!z && key == Th) {
                if (!ordH) z = true;
                else {
                    int i = v * 4 + c, nb = 0;
                    for (int j = 0; j < i; j++) nb += (f2key(row[j]) == Th);
                    z = (nb < rh);
                }
            }
            if (!z && key == Tl) {
                if (!ordL) z = true;
                else {
                    int i = v * 4 + c, nb = 0;
                    for (int j = 0; j < i; j++) nb += (f2key(row[j]) == Tl);
                    z = (nb < rl);
                }
            }
            if (z) vals[c] = 0.0f;
        }
        float4 o; o.x = vals[0]; o.y = vals[1]; o.z = vals[2]; o.w = vals[3];
        orow[v] = o;
    }
}

extern "C" void kernel_launch(void* const* d_in, const int* in_sizes, int n_in,
                              void* d_out, int out_size)
{
    const float* x = (const float*)d_in[0];
    const float* w = (const float*)d_in[1];
    const int* kp  = (n_in >= 3) ? (const int*)d_in[2] : nullptr;

    int Fdim = in_sizes[1];            // weight length = feature dim
    int B    = in_sizes[0] / Fdim;     // rows

    topk_mask_kernel<<<B, THREADS>>>(x, w, kp, (float*)d_out, Fdim);
}

// round 2
// speedup vs baseline: 2.2682x; 2.2682x over previous
#include <cuda_runtime.h>
#include <stdint.h>

#define THREADS 512
#define NBINS   4096
#define CAP     512
#define FDIM    8192
#define EPT     16            // elements per thread
#define VPT     4             // float4 vectors per thread

// Order-preserving float -> uint32 (ascending)
__device__ __forceinline__ unsigned f2key(float f) {
    unsigned u = __float_as_uint(f);
    return u ^ ((unsigned)((int)u >> 31) | 0x80000000u);
}
// Exact inverse
__device__ __forceinline__ float key2f(unsigned k) {
    unsigned m = (~(unsigned)((int)k >> 31)) | 0x80000000u;
    return __uint_as_float(k ^ m);
}

__global__ __launch_bounds__(THREADS, 2)
void topk_mask_kernel(const float* __restrict__ x, const float* __restrict__ w,
                      const int* __restrict__ kp, float* __restrict__ out)
{
    __shared__ unsigned hist[NBINS];
    __shared__ unsigned part[THREADS];
    __shared__ unsigned listKH[CAP], listIH[CAP], listKL[CAP], listIL[CAP];
    __shared__ int s_cntH, s_cntL;
    __shared__ int s_Bh, s_Bl, s_rh, s_rl;
    __shared__ unsigned s_Th, s_Ih, s_Tl, s_Il;
    __shared__ int s_red;
    __shared__ int s_K;

    const int tid  = threadIdx.x;
    const int lane = tid & 31;
    const int warp = tid >> 5;
    const int b    = blockIdx.x;

    if (tid == 0) { s_cntH = 0; s_cntL = 0; s_K = kp ? kp[0] : 64; }
    // clear histogram (4096 words / 512 thr = 2 uint4 each)
    ((uint4*)hist)[tid]          = make_uint4(0,0,0,0);
    ((uint4*)hist)[tid + THREADS]= make_uint4(0,0,0,0);
    __syncthreads();
    const int K = s_K;

    const float4* xr = (const float4*)(x + (size_t)b * FDIM);
    const float4* wr = (const float4*)w;
    float4* orow     = (float4*)(out + (size_t)b * FDIM);

    // ---- Phase 0: load, multiply, key, histogram ----
    unsigned key[EPT];
    #pragma unroll
    for (int k = 0; k < VPT; k++) {
        int v = tid + k * THREADS;
        float4 xv = xr[v];
        float4 wv = wr[v];
        key[4*k+0] = f2key(xv.x * wv.x);
        key[4*k+1] = f2key(xv.y * wv.y);
        key[4*k+2] = f2key(xv.z * wv.z);
        key[4*k+3] = f2key(xv.w * wv.w);
        atomicAdd(&hist[key[4*k+0] >> 20], 1u);
        atomicAdd(&hist[key[4*k+1] >> 20], 1u);
        atomicAdd(&hist[key[4*k+2] >> 20], 1u);
        atomicAdd(&hist[key[4*k+3] >> 20], 1u);
    }
    __syncthreads();

    // ---- Phase 1a: partial sums of 8 bins each ----
    {
        uint4 a = ((const uint4*)hist)[tid*2];
        uint4 c = ((const uint4*)hist)[tid*2+1];
        part[tid] = a.x+a.y+a.z+a.w + c.x+c.y+c.z+c.w;
    }
    __syncthreads();

    // ---- Phase 1b: find boundary bins. warp0 = top (desc), warp1 = bottom (asc) ----
    if (warp == 0) {
        unsigned g = 0;
        #pragma unroll
        for (int p = 0; p < 16; p++) g += part[lane*16 + p];
        unsigned acc = g;
        #pragma unroll
        for (int off = 1; off < 32; off <<= 1) {
            unsigned vv = __shfl_down_sync(0xFFFFFFFFu, acc, off);
            if (lane + off < 32) acc += vv;
        }
        unsigned above = acc - g;   // strictly-above this lane's 128-bin range
        if ((int)above < K && (int)(above + g) >= K) {
            unsigned run = above;
            int base = lane * 16;
            for (int p = 15; p >= 0; --p) {
                unsigned pc = part[base + p];
                if ((int)(run + pc) >= K) {
                    int bb = (base + p) * 8;
                    for (int b8 = 7; b8 >= 0; --b8) {
                        unsigned c = hist[bb + b8];
                        if ((int)(run + c) >= K) { s_Bh = bb + b8; s_rh = K - (int)run; break; }
                        run += c;
                    }
                    break;
                }
                run += pc;
            }
        }
    } else if (warp == 1) {
        unsigned g = 0;
        #pragma unroll
        for (int p = 0; p < 16; p++) g += part[lane*16 + p];
        unsigned acc = g;
        #pragma unroll
        for (int off = 1; off < 32; off <<= 1) {
            unsigned vv = __shfl_up_sync(0xFFFFFFFFu, acc, off);
            if (lane >= off) acc += vv;
        }
        unsigned below = acc - g;   // strictly-below this lane's range
        if ((int)below < K && (int)(below + g) >= K) {
            unsigned run = below;
            int base = lane * 16;
            for (int p = 0; p < 16; ++p) {
                unsigned pc = part[base + p];
                if ((int)(run + pc) >= K) {
                    int bb = (base + p) * 8;
                    for (int b8 = 0; b8 < 8; ++b8) {
                        unsigned c = hist[bb + b8];
                        if ((int)(run + c) >= K) { s_Bl = bb + b8; s_rl = K - (int)run; break; }
                        run += c;
                    }
                    break;
                }
                run += pc;
            }
        }
    }
    __syncthreads();

    // ---- Phase 2: compact boundary-bin candidates (key, idx) ----
    {
        const unsigned Bh = (unsigned)s_Bh, Bl = (unsigned)s_Bl;
        #pragma unroll
        for (int e = 0; e < EPT; e++) {
            unsigned bin = key[e] >> 20;
            unsigned idx = (unsigned)(tid*4 + (e>>2)*2048 + (e&3));
            if (bin == Bh) { int p = atomicAdd(&s_cntH, 1); if (p < CAP) { listKH[p] = key[e]; listIH[p] = idx; } }
            if (bin == Bl) { int p = atomicAdd(&s_cntL, 1); if (p < CAP) { listKL[p] = key[e]; listIL[p] = idx; } }
        }
    }
    __syncthreads();

    const int nH = s_cntH, nL = s_cntL;
    const bool ovH = nH > CAP, ovL = nL > CAP;

    // ---- Phase 3: exact threshold + tie index cutoff (common path: O(n^2) rank) ----
    if (!ovH && tid < nH) {
        unsigned kj = listKH[tid], ij = listIH[tid];
        int rank = 0;
        for (int i = 0; i < nH; i++) {
            unsigned ki = listKH[i], ii = listIH[i];
            rank += (ki > kj) || (ki == kj && ii < ij);
        }
        if (rank == s_rh - 1) { s_Th = kj; s_Ih = ij; }
    }
    if (!ovL && tid < nL) {
        unsigned kj = listKL[tid], ij = listIL[tid];
        int rank = 0;
        for (int i = 0; i < nL; i++) {
            unsigned ki = listKL[i], ii = listIL[i];
            rank += (ki < kj) || (ki == kj && ii < ij);
        }
        if (rank == s_rl - 1) { s_Tl = kj; s_Il = ij; }
    }

    // ---- Rare exact fallback: block-uniform binary search on keys, then on index ----
    if (ovH) {
        unsigned lo = 0, hi = 0xFFFFFFFFu;
        for (int it = 0; it < 32; ++it) {
            unsigned mid = lo + ((hi - lo) >> 1);
            if (tid == 0) s_red = 0;
            __syncthreads();
            int c = 0;
            #pragma unroll
            for (int e = 0; e < EPT; e++) c += (key[e] > mid);
            c = __reduce_add_sync(0xFFFFFFFFu, c);
            if (lane == 0) atomicAdd(&s_red, c);
            __syncthreads();
            int tot = s_red;
            __syncthreads();
            if (tot >= K) lo = mid + 1; else hi = mid;
        }
        unsigned Th = lo;
        // r = K - cntGT(Th)
        if (tid == 0) s_red = 0;
        __syncthreads();
        { int c = 0;
          #pragma unroll
          for (int e = 0; e < EPT; e++) c += (key[e] > Th);
          c = __reduce_add_sync(0xFFFFFFFFu, c);
          if (lane == 0) atomicAdd(&s_red, c); }
        __syncthreads();
        int r = K - s_red;
        __syncthreads();
        unsigned lo2 = 0, hi2 = FDIM - 1;
        for (int it = 0; it < 13; ++it) {
            unsigned mid = lo2 + ((hi2 - lo2) >> 1);
            if (tid == 0) s_red = 0;
            __syncthreads();
            int c = 0;
            #pragma unroll
            for (int e = 0; e < EPT; e++) {
                unsigned idx = (unsigned)(tid*4 + (e>>2)*2048 + (e&3));
                c += (key[e] == Th && idx <= mid);
            }
            c = __reduce_add_sync(0xFFFFFFFFu, c);
            if (lane == 0) atomicAdd(&s_red, c);
            __syncthreads();
            int tot = s_red;
            __syncthreads();
            if (tot >= r) hi2 = mid; else lo2 = mid + 1;
        }
        if (tid == 0) { s_Th = Th; s_Ih = lo2; }
    }
    if (ovL) {
        unsigned lo = 0, hi = 0xFFFFFFFFu;
        for (int it = 0; it < 32; ++it) {
            unsigned mid = lo + ((hi - lo) >> 1);
            if (tid == 0) s_red = 0;
            __syncthreads();
            int c = 0;
            #pragma unroll
            for (int e = 0; e < EPT; e++) c += (key[e] <= mid);
            c = __reduce_add_sync(0xFFFFFFFFu, c);
            if (lane == 0) atomicAdd(&s_red, c);
            __syncthreads();
            int tot = s_red;
            __syncthreads();
            if (tot >= K) hi = mid; else lo = mid + 1;
        }
        unsigned Tl = lo;
        if (tid == 0) s_red = 0;
        __syncthreads();
        { int c = 0;
          #pragma unroll
          for (int e = 0; e < EPT; e++) c += (key[e] < Tl);
          c = __reduce_add_sync(0xFFFFFFFFu, c);
          if (lane == 0) atomicAdd(&s_red, c); }
        __syncthreads();
        int r = K - s_red;
        __syncthreads();
        unsigned lo2 = 0, hi2 = FDIM - 1;
        for (int it = 0; it < 13; ++it) {
            unsigned mid = lo2 + ((hi2 - lo2) >> 1);
            if (tid == 0) s_red = 0;
            __syncthreads();
            int c = 0;
            #pragma unroll
            for (int e = 0; e < EPT; e++) {
                unsigned idx = (unsigned)(tid*4 + (e>>2)*2048 + (e&3));
                c += (key[e] == Tl && idx <= mid);
            }
            c = __reduce_add_sync(0xFFFFFFFFu, c);
            if (lane == 0) atomicAdd(&s_red, c);
            __syncthreads();
            int tot = s_red;
            __syncthreads();
            if (tot >= r) hi2 = mid; else lo2 = mid + 1;
        }
        if (tid == 0) { s_Tl = Tl; s_Il = lo2; }
    }
    __syncthreads();

    // ---- Phase 4: masked write-out ----
    const unsigned Th = s_Th, Ih = s_Ih, Tl = s_Tl, Il = s_Il;
    #pragma unroll
    for (int k = 0; k < VPT; k++) {
        float vals[4];
        #pragma unroll
        for (int c = 0; c < 4; c++) {
            unsigned kk  = key[4*k + c];
            unsigned idx = (unsigned)(tid*4 + k*2048 + c);
            bool z = (kk > Th) || (kk < Tl) ||
                     (kk == Th && idx <= Ih) ||
                     (kk == Tl && idx <= Il);
            vals[c] = z ? 0.0f : key2f(kk);
        }
        float4 o; o.x = vals[0]; o.y = vals[1]; o.z = vals[2]; o.w = vals[3];
        orow[tid + k * THREADS] = o;
    }
}

extern "C" void kernel_launch(void* const* d_in, const int* in_sizes, int n_in,
                              void* d_out, int out_size)
{
    const float* x = (const float*)d_in[0];
    const float* w = (const float*)d_in[1];
    const int* kp  = (n_in >= 3) ? (const int*)d_in[2] : nullptr;

    int Fdim = in_sizes[1];
    int B    = in_sizes[0] / Fdim;

    topk_mask_kernel<<<B, THREADS>>>(x, w, kp, (float*)d_out);
}